// round 2
// baseline (speedup 1.0000x reference)
#include <cuda_runtime.h>

#define N_PTS 65536
#define KNN   32
#define NKP   15
#define CIN   64
#define COUT  128
#define TM    32
#define NTHR  256
#define INV_SIGMA 10.0f

// ---- shared memory layout (in 4-byte words) ----
#define SZ_WEIGHTED (TM * NKP * CIN)          // 30720 : weighted[TM][960]
#define OFF_UNION   (SZ_WEIGHTED)
#define SZ_INFL     (TM * KNN * 16)           // 16384 : infl[TM][32][16] (phase1) / w_s[64][128] (phase2, 8192 words)
#define OFF_NB      (OFF_UNION + SZ_INFL)
#define SZ_NB       (TM * KNN)                // 1024 ints
#define OFF_KP      (OFF_NB + SZ_NB)
#define SMEM_WORDS  (OFF_KP + 48)
#define SMEM_BYTES  (SMEM_WORDS * 4)          // 192704 bytes

__device__ int g_nb_is64;

// neighbors may be int64 (reference declares int64) or int32 (JAX without x64).
// Values are < 65536, so if int64, every odd 32-bit word (high half, LE) is 0.
// For int32 random indices, P(64K consecutive odd-position values all zero) ~ 0.
__global__ void detect_idx_kernel(const int* __restrict__ nbw) {
    __shared__ int found;
    if (threadIdx.x == 0) found = 0;
    __syncthreads();
    int f = 0;
    for (int i = threadIdx.x; i < 65536; i += blockDim.x) {
        if (nbw[2 * i + 1] != 0) f = 1;   // safe: int32 buffer has 2097152 words
    }
    if (f) found = 1;
    __syncthreads();
    if (threadIdx.x == 0) g_nb_is64 = found ? 0 : 1;
}

__global__ __launch_bounds__(NTHR, 1)
void kpconv_kernel(const float* __restrict__ pos,
                   const float* __restrict__ feats,
                   const float* __restrict__ kpts,
                   const float* __restrict__ Wg,
                   const int*   __restrict__ nbw,
                   float*       __restrict__ out)
{
    extern __shared__ float sm[];
    float* weighted = sm;                 // [TM][NKP*CIN]
    float* infl     = sm + OFF_UNION;     // [TM][KNN][16], aliased by w_s in phase 2
    float* w_s      = infl;               // [CIN][COUT] for current kp
    int*   nb_s     = (int*)(sm + OFF_NB);
    float* kp_s     = sm + OFF_KP;

    const int tid  = threadIdx.x;
    const int lane = tid & 31;
    const int warp = tid >> 5;
    const int base = blockIdx.x * TM;
    const int scale = 1 + g_nb_is64;      // word stride into neighbor buffer

    if (tid < NKP * 3) kp_s[tid] = kpts[tid];
    __syncthreads();

    // ---------------- Phase 1a: influences + neighbor indices ----------------
    // warp owns points m = warp*4 .. warp*4+3 ; lane = neighbor index k
    #pragma unroll
    for (int mi = 0; mi < 4; mi++) {
        int m = warp * 4 + mi;
        int n = base + m;
        int nbi = nbw[(n * KNN + lane) * scale];
        nb_s[m * KNN + lane] = nbi;
        float px = pos[3 * n],   py = pos[3 * n + 1],   pz = pos[3 * n + 2];
        float rx = pos[3 * nbi]     - px;
        float ry = pos[3 * nbi + 1] - py;
        float rz = pos[3 * nbi + 2] - pz;
        float iv[16];
        #pragma unroll
        for (int q = 0; q < NKP; q++) {
            float dx = rx - kp_s[3 * q];
            float dy = ry - kp_s[3 * q + 1];
            float dz = rz - kp_s[3 * q + 2];
            float dist = sqrtf(fmaf(dx, dx, fmaf(dy, dy, dz * dz)));
            iv[q] = fmaxf(0.0f, fmaf(-dist, INV_SIGMA, 1.0f));
        }
        iv[15] = 0.0f;
        float4* dst = (float4*)&infl[(m * KNN + lane) * 16];
        dst[0] = make_float4(iv[0],  iv[1],  iv[2],  iv[3]);
        dst[1] = make_float4(iv[4],  iv[5],  iv[6],  iv[7]);
        dst[2] = make_float4(iv[8],  iv[9],  iv[10], iv[11]);
        dst[3] = make_float4(iv[12], iv[13], iv[14], iv[15]);
    }
    __syncthreads();

    // ---------------- Phase 1b: weighted[m][kp][c] = sum_k infl * feats -----
    // lane owns channels (2*lane, 2*lane+1); 15 kp accumulators in registers
    #pragma unroll
    for (int mi = 0; mi < 4; mi++) {
        int m = warp * 4 + mi;
        float2 acc[NKP];
        #pragma unroll
        for (int q = 0; q < NKP; q++) acc[q] = make_float2(0.f, 0.f);
        const int*    nbm   = nb_s + m * KNN;
        const float4* inflm = (const float4*)&infl[m * KNN * 16];
        #pragma unroll 4
        for (int k = 0; k < KNN; k++) {
            int nbi = nbm[k];
            float2 f = *(const float2*)&feats[nbi * CIN + 2 * lane];
            float4 q0 = inflm[k * 4 + 0];
            float4 q1 = inflm[k * 4 + 1];
            float4 q2 = inflm[k * 4 + 2];
            float4 q3 = inflm[k * 4 + 3];
            float wv[16] = {q0.x, q0.y, q0.z, q0.w, q1.x, q1.y, q1.z, q1.w,
                            q2.x, q2.y, q2.z, q2.w, q3.x, q3.y, q3.z, q3.w};
            #pragma unroll
            for (int q = 0; q < NKP; q++) {
                acc[q].x = fmaf(wv[q], f.x, acc[q].x);
                acc[q].y = fmaf(wv[q], f.y, acc[q].y);
            }
        }
        #pragma unroll
        for (int q = 0; q < NKP; q++)
            *(float2*)&weighted[m * (NKP * CIN) + q * CIN + 2 * lane] = acc[q];
    }

    // ---------------- Phase 2: out[TM][COUT] = weighted @ W ------------------
    // thread tile: 4 m (m = warp*4+mi) x 4 d (d = lane*4 .. +3)
    const int d0 = lane * 4;
    float acc2[4][4];
    #pragma unroll
    for (int a = 0; a < 4; a++)
        #pragma unroll
        for (int b = 0; b < 4; b++) acc2[a][b] = 0.f;

    for (int q = 0; q < NKP; q++) {
        __syncthreads();  // previous consumers of w_s / infl done
        const float4* wg4 = (const float4*)(Wg + q * CIN * COUT);
        float4* ws4 = (float4*)w_s;
        #pragma unroll
        for (int i = 0; i < 8; i++) ws4[tid + i * NTHR] = wg4[tid + i * NTHR];
        __syncthreads();

        const float* wb0 = weighted + (warp * 4 + 0) * (NKP * CIN) + q * CIN;
        const float* wb1 = wb0 + NKP * CIN;
        const float* wb2 = wb1 + NKP * CIN;
        const float* wb3 = wb2 + NKP * CIN;
        #pragma unroll 4
        for (int c4 = 0; c4 < CIN; c4 += 4) {
            float4 a0 = *(const float4*)(wb0 + c4);
            float4 a1 = *(const float4*)(wb1 + c4);
            float4 a2 = *(const float4*)(wb2 + c4);
            float4 a3 = *(const float4*)(wb3 + c4);
            float am[4][4] = {{a0.x, a0.y, a0.z, a0.w},
                              {a1.x, a1.y, a1.z, a1.w},
                              {a2.x, a2.y, a2.z, a2.w},
                              {a3.x, a3.y, a3.z, a3.w}};
            #pragma unroll
            for (int cc = 0; cc < 4; cc++) {
                float4 b = *(const float4*)&w_s[(c4 + cc) * COUT + d0];
                #pragma unroll
                for (int mi = 0; mi < 4; mi++) {
                    acc2[mi][0] = fmaf(am[mi][cc], b.x, acc2[mi][0]);
                    acc2[mi][1] = fmaf(am[mi][cc], b.y, acc2[mi][1]);
                    acc2[mi][2] = fmaf(am[mi][cc], b.z, acc2[mi][2]);
                    acc2[mi][3] = fmaf(am[mi][cc], b.w, acc2[mi][3]);
                }
            }
        }
    }

    #pragma unroll
    for (int mi = 0; mi < 4; mi++) {
        int n = base + warp * 4 + mi;
        *(float4*)&out[n * COUT + d0] =
            make_float4(acc2[mi][0], acc2[mi][1], acc2[mi][2], acc2[mi][3]);
    }
}

extern "C" void kernel_launch(void* const* d_in, const int* in_sizes, int n_in,
                              void* d_out, int out_size)
{
    const float* pos   = (const float*)d_in[0];
    const float* feats = (const float*)d_in[1];
    const float* kpts  = (const float*)d_in[2];
    const float* Wg    = (const float*)d_in[3];
    const int*   nbw   = (const int*)d_in[4];   // int32 view; stride resolved at runtime
    float* out = (float*)d_out;

    cudaFuncSetAttribute(kpconv_kernel,
                         cudaFuncAttributeMaxDynamicSharedMemorySize, SMEM_BYTES);

    detect_idx_kernel<<<1, 256>>>(nbw);
    kpconv_kernel<<<N_PTS / TM, NTHR, SMEM_BYTES>>>(pos, feats, kpts, Wg, nbw, out);
}

// round 5
// speedup vs baseline: 1.5328x; 1.5328x over previous
#include <cuda_runtime.h>
#include <cstdint>

#define N_PTS 65536
#define KNN   32
#define NKP   15
#define CIN   64
#define COUT  128
#define TM    32
#define NTHR  256
#define INV_SIGMA 10.0f

// ---- shared memory layout (in 4-byte words) ----
#define WSTRIDE     964                        // padded 960 -> conflict-free mma A loads
#define SZ_WEIGHTED (TM * WSTRIDE)             // 30848
#define OFF_UNION   (SZ_WEIGHTED)
#define SZ_INFL     (TM * KNN * 16)            // 16384 ; phase2 aliases w_s[64][136]=8704
#define BSTRIDE     136                        // padded 128 -> conflict-free mma B loads
#define OFF_NB      (OFF_UNION + SZ_INFL)
#define SZ_NB       (TM * KNN)
#define OFF_KP      (OFF_NB + SZ_NB)
#define SMEM_WORDS  (OFF_KP + 48)
#define SMEM_BYTES  (SMEM_WORDS * 4)           // 193216 bytes

__device__ int g_nb_is64;

// neighbors may be int64 (reference dtype) or int32 (JAX default). Values < 65536,
// so int64 => every odd 32-bit word is 0. Detect once.
__global__ void detect_idx_kernel(const int* __restrict__ nbw) {
    __shared__ int found;
    if (threadIdx.x == 0) found = 0;
    __syncthreads();
    int f = 0;
    for (int i = threadIdx.x; i < 65536; i += blockDim.x)
        if (nbw[2 * i + 1] != 0) f = 1;
    if (f) found = 1;
    __syncthreads();
    if (threadIdx.x == 0) g_nb_is64 = found ? 0 : 1;
}

__device__ __forceinline__ uint32_t tf32_rna(float x) {
    uint32_t y;
    asm("cvt.rna.tf32.f32 %0, %1;" : "=r"(y) : "f"(x));
    return y;
}

__device__ __forceinline__ void mma_tf32(float* d, uint32_t a0, uint32_t a1,
                                         uint32_t a2, uint32_t a3,
                                         uint32_t b0, uint32_t b1) {
    asm volatile(
        "mma.sync.aligned.m16n8k8.row.col.f32.tf32.tf32.f32 "
        "{%0,%1,%2,%3}, {%4,%5,%6,%7}, {%8,%9}, {%0,%1,%2,%3};\n"
        : "+f"(d[0]), "+f"(d[1]), "+f"(d[2]), "+f"(d[3])
        : "r"(a0), "r"(a1), "r"(a2), "r"(a3), "r"(b0), "r"(b1));
}

__global__ __launch_bounds__(NTHR, 1)
void kpconv_kernel(const float* __restrict__ pos,
                   const float* __restrict__ feats,
                   const float* __restrict__ kpts,
                   const float* __restrict__ Wg,
                   const int*   __restrict__ nbw,
                   float*       __restrict__ out)
{
    extern __shared__ float sm[];
    float* weighted = sm;                 // [TM][WSTRIDE] (values tf32-rounded)
    float* infl     = sm + OFF_UNION;     // [TM][KNN][16], aliased by w_s in phase 2
    float* w_s      = infl;               // [CIN][BSTRIDE] for current kp (tf32)
    int*   nb_s     = (int*)(sm + OFF_NB);
    float* kp_s     = sm + OFF_KP;

    const int tid  = threadIdx.x;
    const int lane = tid & 31;
    const int warp = tid >> 5;
    const int base = blockIdx.x * TM;
    const int scale = 1 + g_nb_is64;

    if (tid < NKP * 3) kp_s[tid] = kpts[tid];
    __syncthreads();

    // ---------------- Phase 1a: influences + neighbor indices ----------------
    #pragma unroll
    for (int mi = 0; mi < 4; mi++) {
        int m = warp * 4 + mi;
        int n = base + m;
        int nbi = nbw[(n * KNN + lane) * scale];
        nb_s[m * KNN + lane] = nbi;
        float px = pos[3 * n],   py = pos[3 * n + 1],   pz = pos[3 * n + 2];
        float rx = pos[3 * nbi]     - px;
        float ry = pos[3 * nbi + 1] - py;
        float rz = pos[3 * nbi + 2] - pz;
        float iv[16];
        #pragma unroll
        for (int q = 0; q < NKP; q++) {
            float dx = rx - kp_s[3 * q];
            float dy = ry - kp_s[3 * q + 1];
            float dz = rz - kp_s[3 * q + 2];
            float dist = sqrtf(fmaf(dx, dx, fmaf(dy, dy, dz * dz)));
            iv[q] = fmaxf(0.0f, fmaf(-dist, INV_SIGMA, 1.0f));
        }
        iv[15] = 0.0f;
        float4* dst = (float4*)&infl[(m * KNN + lane) * 16];
        dst[0] = make_float4(iv[0],  iv[1],  iv[2],  iv[3]);
        dst[1] = make_float4(iv[4],  iv[5],  iv[6],  iv[7]);
        dst[2] = make_float4(iv[8],  iv[9],  iv[10], iv[11]);
        dst[3] = make_float4(iv[12], iv[13], iv[14], iv[15]);
    }
    __syncthreads();

    // ---------- Phase 1b: weighted[m][kp*64+c] = sum_k infl * feats (fp32) ----
    // lane owns channels (2*lane, 2*lane+1); results tf32-rounded on store
    #pragma unroll
    for (int mi = 0; mi < 4; mi++) {
        int m = warp * 4 + mi;
        float2 acc[NKP];
        #pragma unroll
        for (int q = 0; q < NKP; q++) acc[q] = make_float2(0.f, 0.f);
        const int*    nbm   = nb_s + m * KNN;
        const float4* inflm = (const float4*)&infl[m * KNN * 16];
        #pragma unroll 4
        for (int k = 0; k < KNN; k++) {
            int nbi = nbm[k];
            float2 f = *(const float2*)&feats[nbi * CIN + 2 * lane];
            float4 q0 = inflm[k * 4 + 0];
            float4 q1 = inflm[k * 4 + 1];
            float4 q2 = inflm[k * 4 + 2];
            float4 q3 = inflm[k * 4 + 3];
            float wv[16] = {q0.x, q0.y, q0.z, q0.w, q1.x, q1.y, q1.z, q1.w,
                            q2.x, q2.y, q2.z, q2.w, q3.x, q3.y, q3.z, q3.w};
            #pragma unroll
            for (int q = 0; q < NKP; q++) {
                acc[q].x = fmaf(wv[q], f.x, acc[q].x);
                acc[q].y = fmaf(wv[q], f.y, acc[q].y);
            }
        }
        #pragma unroll
        for (int q = 0; q < NKP; q++) {
            uint32_t ux = tf32_rna(acc[q].x);
            uint32_t uy = tf32_rna(acc[q].y);
            uint2* dst = (uint2*)&weighted[m * WSTRIDE + q * CIN + 2 * lane];
            *dst = make_uint2(ux, uy);
        }
    }

    // ------------- Phase 2: out[32][128] = weighted @ W via tf32 mma ---------
    // warp grid: 2 (m) x 4 (n). warp tile 16x32, four m16n8k8 per k-step.
    const int warp_m = warp >> 2;          // 0..1
    const int warp_n = warp & 3;           // 0..3
    const int lane4  = lane & 3;
    const int laneg  = lane >> 2;

    const uint32_t* Abase =
        (const uint32_t*)(weighted + (warp_m * 16 + laneg) * WSTRIDE + lane4);
    const float* Bbase = w_s + lane4 * BSTRIDE + warp_n * 32 + laneg;

    float acc2[4][4];
    #pragma unroll
    for (int nt = 0; nt < 4; nt++)
        #pragma unroll
        for (int i = 0; i < 4; i++) acc2[nt][i] = 0.f;

    for (int q = 0; q < NKP; q++) {
        __syncthreads();  // previous consumers of w_s / infl done
        // load W[q] (64x128) into w_s[64][136] with tf32 rounding
        const float4* wg4 = (const float4*)(Wg + q * CIN * COUT);
        #pragma unroll
        for (int i = 0; i < 8; i++) {
            int e4 = i * NTHR + tid;         // float4 index, 0..2047
            int c  = e4 >> 5;
            int d4 = e4 & 31;
            float4 v = wg4[e4];
            uint4 u = make_uint4(tf32_rna(v.x), tf32_rna(v.y),
                                 tf32_rna(v.z), tf32_rna(v.w));
            *(uint4*)&w_s[c * BSTRIDE + d4 * 4] = u;
        }
        __syncthreads();

        #pragma unroll
        for (int c8 = 0; c8 < 8; c8++) {
            const uint32_t* A = Abase + q * CIN + c8 * 8;
            uint32_t a0 = A[0];
            uint32_t a1 = A[8 * WSTRIDE];
            uint32_t a2 = A[4];
            uint32_t a3 = A[8 * WSTRIDE + 4];
            const float* B = Bbase + c8 * 8 * BSTRIDE;
            #pragma unroll
            for (int nt = 0; nt < 4; nt++) {
                uint32_t b0 = __float_as_uint(B[nt * 8]);
                uint32_t b1 = __float_as_uint(B[nt * 8 + 4 * BSTRIDE]);
                mma_tf32(acc2[nt], a0, a1, a2, a3, b0, b1);
            }
        }
    }

    // epilogue: thread owns rows (m0+laneg, +8), cols (n0+nt*8+lane4*2, +1)
    const int r0 = base + warp_m * 16 + laneg;
    #pragma unroll
    for (int nt = 0; nt < 4; nt++) {
        int col = warp_n * 32 + nt * 8 + lane4 * 2;
        *(float2*)&out[r0 * COUT + col] =
            make_float2(acc2[nt][0], acc2[nt][1]);
        *(float2*)&out[(r0 + 8) * COUT + col] =
            make_float2(acc2[nt][2], acc2[nt][3]);
    }
}

extern "C" void kernel_launch(void* const* d_in, const int* in_sizes, int n_in,
                              void* d_out, int out_size)
{
    const float* pos   = (const float*)d_in[0];
    const float* feats = (const float*)d_in[1];
    const float* kpts  = (const float*)d_in[2];
    const float* Wg    = (const float*)d_in[3];
    const int*   nbw   = (const int*)d_in[4];
    float* out = (float*)d_out;

    cudaFuncSetAttribute(kpconv_kernel,
                         cudaFuncAttributeMaxDynamicSharedMemorySize, SMEM_BYTES);

    detect_idx_kernel<<<1, 256>>>(nbw);
    kpconv_kernel<<<N_PTS / TM, NTHR, SMEM_BYTES>>>(pos, feats, kpts, Wg, nbw, out);
}